// round 7
// baseline (speedup 1.0000x reference)
#include <cuda_runtime.h>
#include <cuda_bf16.h>

#define N_NODES 1024
#define D_EMB 64
#define F_IN 128
#define H_DIM 64
#define N_CLS 8
#define EPAD 68
#define NBLK 16          // 1024/64 node blocks
#define NPAIR (NBLK * (NBLK + 1) / 2)   // 136
#define GRID 148         // one block per SM (B200: 148 SMs)
#define THREADS 512
#define PAIR_FLOATS (4 * 64 * EPAD + 64)   // 17,472 floats = 69,888 B per pair

// Scratch (no cudaMalloc allowed)
__device__ float g_a[N_NODES * H_DIM];     // embed @ W1[:64] + b1
__device__ float g_b[N_NODES * H_DIM];     // embed @ W1[64:]
__device__ float g_xw[N_NODES * H_DIM];    // x @ Wg1
__device__ float g_m[N_NODES * N_NODES];   // masked_adj = adj .* sym_mask
__device__ float g_pool[H_DIM];            // sum over nodes of relu(m @ xw)
__device__ unsigned long long g_bar;       // monotonic grid-barrier ticket

// ---------------------------------------------------------------------------
// Device-wide barrier: ticket/generation on a monotonic counter. No reset
// needed between graph replays; all GRID blocks co-resident (1 block/SM).
// ---------------------------------------------------------------------------
__device__ __forceinline__ void grid_sync()
{
    __syncthreads();
    if (threadIdx.x == 0) {
        __threadfence();
        const unsigned long long ticket = atomicAdd(&g_bar, 1ULL);
        const unsigned long long target =
            (ticket / GRID + 1ULL) * (unsigned long long)GRID;
        while (atomicAdd(&g_bar, 0ULL) < target) { __nanosleep(64); }
        __threadfence();
    }
    __syncthreads();
}

__device__ __forceinline__ float gate_of(float u, float la, float invb)
{
    const float z = (__logf(u) - __logf(1.f - u) + la) * invb;
    return __frcp_rn(1.f + __expf(-z));
}

extern __shared__ float smem[];

__global__ __launch_bounds__(THREADS) void fused_kernel(
    const float* __restrict__ x,     const float* __restrict__ embed,
    const float* __restrict__ adj,   const float* __restrict__ tmp,
    const float* __restrict__ noise, const float* __restrict__ W1,
    const float* __restrict__ b1,    const float* __restrict__ W2,
    const float* __restrict__ b2,    const float* __restrict__ Wg1,
    const float* __restrict__ Wg2,   float* __restrict__ out)
{
    const int t = threadIdx.x;

    // ======================= Phase 0: per-node precompute ===================
    // 128 units of 8 rows; 512 threads: col = t&63, row r = t>>6 (1 row each).
    {
        float* se = smem;              // 8 x 64
        float* sx = smem + 8 * 64;     // 8 x 128

        if (blockIdx.x == 0 && t < H_DIM) g_pool[t] = 0.f;

        const int col = t & 63;
        const int r   = t >> 6;        // 0..7

        for (int u = blockIdx.x; u < 128; u += gridDim.x) {
            const int i0 = u * 8;
            __syncthreads();
            se[t & 511] = embed[i0 * D_EMB + t];              // 512 = 8*64
            #pragma unroll
            for (int p = 0; p < 2; p++)
                sx[t + p * 512] = x[i0 * F_IN + t + p * 512]; // 1024 = 8*128
            __syncthreads();

            float va = b1[col], vb = 0.f, vx = 0.f;
            #pragma unroll 4
            for (int k = 0; k < D_EMB; k++) {
                const float e = se[r * D_EMB + k];
                va = fmaf(e, W1[k * H_DIM + col], va);
                vb = fmaf(e, W1[(D_EMB + k) * H_DIM + col], vb);
            }
            #pragma unroll 4
            for (int k = 0; k < F_IN; k++)
                vx = fmaf(sx[r * F_IN + k], Wg1[k * H_DIM + col], vx);

            g_a [(i0 + r) * H_DIM + col] = va;
            g_b [(i0 + r) * H_DIM + col] = vb;
            g_xw[(i0 + r) * H_DIM + col] = vx;
        }
    }
    grid_sync();

    // ================== Phase 1: symmetric edge gate -> g_m =================
    // 136 upper-triangle 64x64 block pairs. 512 threads = two independent
    // 256-thread halves, each with its own smem slab + its own pair.
    // v = 2*bid + sub: halves of one block are both-active or both-inactive,
    // so the shared __syncthreads below is deadlock-free. 2*GRID=296 >= 136,
    // so a single shot covers all pairs.
    {
        const int sub = t >> 8;          // 0 or 1
        const int ts  = t & 255;         // thread id within half
        float* base = smem + sub * PAIR_FLOATS;
        float* sAi = base;
        float* sBj = sAi + 64 * EPAD;
        float* sAj = sBj + 64 * EPAD;
        float* sBi = sAj + 64 * EPAD;
        float* sw2 = sBi + 64 * EPAD;

        const int v = blockIdx.x * 2 + sub;
        if (v < NPAIR) {
            int b = v, bi = 0;
            while (b >= NBLK - bi) { b -= NBLK - bi; bi++; }
            const int bj = bi + b;
            const int i0 = bi * 64, j0 = bj * 64;

            #pragma unroll
            for (int p = 0; p < 16; p++) {
                const int idx = ts + p * 256;
                const int r = idx >> 6, k = idx & 63;
                sAi[k * EPAD + r] = g_a[(i0 + r) * H_DIM + k];
                sBi[k * EPAD + r] = g_b[(i0 + r) * H_DIM + k];
                sAj[k * EPAD + r] = g_a[(j0 + r) * H_DIM + k];
                sBj[k * EPAD + r] = g_b[(j0 + r) * H_DIM + k];
            }
            if (ts < 64) sw2[ts] = W2[ts];
            __syncthreads();

            const int tx = ts & 15, ty = ts >> 4;
            const float b2s = b2[0];
            float acc1[4][4], acc2[4][4];
            #pragma unroll
            for (int r = 0; r < 4; r++)
                #pragma unroll
                for (int c = 0; c < 4; c++) { acc1[r][c] = b2s; acc2[r][c] = b2s; }

            #pragma unroll 2
            for (int k = 0; k < 64; k++) {
                const float4 ai  = *(const float4*)&sAi[k * EPAD + 4 * ty];
                const float4 bj4 = *(const float4*)&sBj[k * EPAD + 4 * tx];
                const float4 aj  = *(const float4*)&sAj[k * EPAD + 4 * tx];
                const float4 bi4 = *(const float4*)&sBi[k * EPAD + 4 * ty];
                const float w = sw2[k];
                const float av1[4] = {ai.x, ai.y, ai.z, ai.w};
                const float bv1[4] = {bj4.x, bj4.y, bj4.z, bj4.w};
                const float av2[4] = {aj.x, aj.y, aj.z, aj.w};
                const float bv2[4] = {bi4.x, bi4.y, bi4.z, bi4.w};
                #pragma unroll
                for (int r = 0; r < 4; r++)
                    #pragma unroll
                    for (int c = 0; c < 4; c++) {
                        acc1[r][c] = fmaf(fmaxf(av1[r] + bv1[c], 0.f), w, acc1[r][c]);
                        acc2[c][r] = fmaf(fmaxf(av2[c] + bv2[r], 0.f), w, acc2[c][r]);
                    }
            }

            const float invb = __frcp_rn(tmp[0]);
            float g1[4][4], g2[4][4];
            #pragma unroll
            for (int r = 0; r < 4; r++) {
                const int row = i0 + 4 * ty + r;
                const float4 nu = *(const float4*)&noise[(size_t)row * N_NODES + j0 + 4 * tx];
                g1[r][0] = gate_of(nu.x, acc1[r][0], invb);
                g1[r][1] = gate_of(nu.y, acc1[r][1], invb);
                g1[r][2] = gate_of(nu.z, acc1[r][2], invb);
                g1[r][3] = gate_of(nu.w, acc1[r][3], invb);
            }
            #pragma unroll
            for (int c = 0; c < 4; c++) {
                const int row = j0 + 4 * tx + c;
                const float4 nu = *(const float4*)&noise[(size_t)row * N_NODES + i0 + 4 * ty];
                g2[c][0] = gate_of(nu.x, acc2[c][0], invb);
                g2[c][1] = gate_of(nu.y, acc2[c][1], invb);
                g2[c][2] = gate_of(nu.z, acc2[c][2], invb);
                g2[c][3] = gate_of(nu.w, acc2[c][3], invb);
            }
            #pragma unroll
            for (int r = 0; r < 4; r++) {
                const int row = i0 + 4 * ty + r;
                const float4 av = *(const float4*)&adj[(size_t)row * N_NODES + j0 + 4 * tx];
                float4 o;
                o.x = av.x * 0.5f * (g1[r][0] + g2[0][r]);
                o.y = av.y * 0.5f * (g1[r][1] + g2[1][r]);
                o.z = av.z * 0.5f * (g1[r][2] + g2[2][r]);
                o.w = av.w * 0.5f * (g1[r][3] + g2[3][r]);
                *(float4*)&g_m[(size_t)row * N_NODES + j0 + 4 * tx] = o;
            }
            #pragma unroll
            for (int c = 0; c < 4; c++) {
                const int row = j0 + 4 * tx + c;
                const float4 av = *(const float4*)&adj[(size_t)row * N_NODES + i0 + 4 * ty];
                float4 o;
                o.x = av.x * 0.5f * (g1[0][c] + g2[c][0]);
                o.y = av.y * 0.5f * (g1[1][c] + g2[c][1]);
                o.z = av.z * 0.5f * (g1[2][c] + g2[c][2]);
                o.w = av.w * 0.5f * (g1[3][c] + g2[c][3]);
                *(float4*)&g_m[(size_t)row * N_NODES + i0 + 4 * ty] = o;
            }
        }
    }
    grid_sync();

    // =============== Phase 2: pool += sum_rows relu(m @ xw) =================
    // 64 units of 16 rows; 512 threads: rr = t>>5 (0..15), 2 cols each.
    {
        float* s_xw  = smem;            // 64 x 64
        float* s_red = smem + 64 * 64;  // 16 x 64

        const int fx = (t & 31) * 2;
        const int rr = t >> 5;

        for (int u = blockIdx.x; u < 64; u += gridDim.x) {
            const int i0 = u * 16;
            float a0 = 0.f, a1 = 0.f;
            const float4* mrow = (const float4*)&g_m[(size_t)(i0 + rr) * N_NODES];

            for (int k0 = 0; k0 < N_NODES; k0 += 64) {
                __syncthreads();
                #pragma unroll
                for (int p = 0; p < 2; p++) {
                    const int idx = (t + p * 512) * 4;
                    *(float4*)&s_xw[idx] = *(const float4*)&g_xw[k0 * H_DIM + idx];
                }
                __syncthreads();
                #pragma unroll
                for (int kk = 0; kk < 64; kk += 4) {
                    const float4 mv = __ldg(&mrow[(k0 + kk) >> 2]);
                    const float2 x0 = *(const float2*)&s_xw[(kk + 0) * 64 + fx];
                    const float2 x1 = *(const float2*)&s_xw[(kk + 1) * 64 + fx];
                    const float2 x2 = *(const float2*)&s_xw[(kk + 2) * 64 + fx];
                    const float2 x3 = *(const float2*)&s_xw[(kk + 3) * 64 + fx];
                    a0 = fmaf(mv.x, x0.x, a0); a1 = fmaf(mv.x, x0.y, a1);
                    a0 = fmaf(mv.y, x1.x, a0); a1 = fmaf(mv.y, x1.y, a1);
                    a0 = fmaf(mv.z, x2.x, a0); a1 = fmaf(mv.z, x2.y, a1);
                    a0 = fmaf(mv.w, x3.x, a0); a1 = fmaf(mv.w, x3.y, a1);
                }
            }
            s_red[rr * 64 + fx]     = fmaxf(a0, 0.f);
            s_red[rr * 64 + fx + 1] = fmaxf(a1, 0.f);
            __syncthreads();
            if (t < 64) {
                float s = 0.f;
                #pragma unroll
                for (int r = 0; r < 16; r++) s += s_red[r * 64 + t];
                atomicAdd(&g_pool[t], s);
            }
            __syncthreads();
        }
    }
    grid_sync();

    // ================= Phase 3: logits + softmax (block 0) ==================
    if (blockIdx.x == 0) {
        float* sp   = smem;
        float* slog = smem + 64;
        float* sexp = smem + 72;

        if (t < 64) sp[t] = g_pool[t] * (1.0f / (float)N_NODES);
        __syncthreads();
        if (t < N_CLS) {
            float lg = 0.f;
            #pragma unroll 8
            for (int k = 0; k < 64; k++) lg += sp[k] * Wg2[k * N_CLS + t];
            slog[t] = lg;
        }
        __syncthreads();
        if (t < N_CLS) {
            float m = slog[0];
            #pragma unroll
            for (int cc = 1; cc < N_CLS; cc++) m = fmaxf(m, slog[cc]);
            sexp[t] = expf(slog[t] - m);
        }
        __syncthreads();
        if (t < N_CLS) {
            float sum = 0.f;
            #pragma unroll
            for (int cc = 0; cc < N_CLS; cc++) sum += sexp[cc];
            out[t] = sexp[t] / sum;
        }
    }
}

// ---------------------------------------------------------------------------
extern "C" void kernel_launch(void* const* d_in, const int* in_sizes, int n_in,
                              void* d_out, int out_size)
{
    const float* x     = (const float*)d_in[0];
    const float* embed = (const float*)d_in[1];
    const float* adj   = (const float*)d_in[2];
    const float* tmp   = (const float*)d_in[3];
    const float* noise = (const float*)d_in[4];
    // d_in[5] = label (int), unused by the forward pass
    const float* W1    = (const float*)d_in[6];
    const float* b1    = (const float*)d_in[7];
    const float* W2    = (const float*)d_in[8];
    const float* b2    = (const float*)d_in[9];
    const float* Wg1   = (const float*)d_in[10];
    const float* Wg2   = (const float*)d_in[11];
    float* out = (float*)d_out;

    const int smem_bytes = 2 * PAIR_FLOATS * (int)sizeof(float); // 139,776 B
    cudaFuncSetAttribute(fused_kernel,
                         cudaFuncAttributeMaxDynamicSharedMemorySize,
                         smem_bytes);

    fused_kernel<<<GRID, THREADS, smem_bytes>>>(
        x, embed, adj, tmp, noise, W1, b1, W2, b2, Wg1, Wg2, out);
}

// round 8
// speedup vs baseline: 1.2902x; 1.2902x over previous
#include <cuda_runtime.h>
#include <cuda_bf16.h>

#define N_NODES 1024
#define D_EMB 64
#define F_IN 128
#define H_DIM 64
#define N_CLS 8
#define NBLK 16                          // 1024/64 node blocks
#define NPAIR (NBLK * (NBLK + 1) / 2)    // 136
#define NHALF (2 * NPAIR)                // 272 half-pair units
#define GRID 296                         // 2 persistent blocks per SM (148 SMs)
#define THREADS 256
#define PAD32 36                         // stride for 32-row transposed tiles
#define PAD64 68                         // stride for 64-row transposed tiles

// Scratch (no cudaMalloc allowed)
__device__ float g_a[N_NODES * H_DIM];     // embed @ W1[:64] + b1
__device__ float g_b[N_NODES * H_DIM];     // embed @ W1[64:]
__device__ float g_xw[N_NODES * H_DIM];    // x @ Wg1
__device__ float g_m[N_NODES * N_NODES];   // masked_adj = adj .* sym_mask
__device__ float g_pool[H_DIM];            // sum over nodes of relu(m @ xw)
__device__ unsigned long long g_bar;       // monotonic grid-barrier ticket

// ---------------------------------------------------------------------------
// Device-wide barrier (ticket/generation, monotonic counter; deterministic
// across graph replays). All GRID blocks are co-resident: per SM the 2 blocks
// need 512 thr / ~107KB smem / ~40k regs, and even a skewed 3-block placement
// fits, so every block is scheduled before any can finish.
// ---------------------------------------------------------------------------
__device__ __forceinline__ void grid_sync()
{
    __syncthreads();
    if (threadIdx.x == 0) {
        __threadfence();
        const unsigned long long ticket = atomicAdd(&g_bar, 1ULL);
        const unsigned long long target =
            (ticket / GRID + 1ULL) * (unsigned long long)GRID;
        while (atomicAdd(&g_bar, 0ULL) < target) { __nanosleep(64); }
        __threadfence();
    }
    __syncthreads();
}

__device__ __forceinline__ float gate_of(float u, float la, float invb)
{
    const float z = (__logf(u) - __logf(1.f - u) + la) * invb;
    return __frcp_rn(1.f + __expf(-z));
}

extern __shared__ float smem[];

__global__ __launch_bounds__(THREADS) void fused_kernel(
    const float* __restrict__ x,     const float* __restrict__ embed,
    const float* __restrict__ adj,   const float* __restrict__ tmp,
    const float* __restrict__ noise, const float* __restrict__ W1,
    const float* __restrict__ b1,    const float* __restrict__ W2,
    const float* __restrict__ b2,    const float* __restrict__ Wg1,
    const float* __restrict__ Wg2,   float* __restrict__ out)
{
    const int t = threadIdx.x;

    // ======================= Phase 0: per-node precompute ===================
    // 256 units of 4 rows; col = t&63, row r = t>>6 (0..3).
    {
        float* se = smem;              // 4 x 64
        float* sx = smem + 4 * 64;     // 4 x 128

        if (blockIdx.x == 0 && t < H_DIM) g_pool[t] = 0.f;

        const int col = t & 63;
        const int r   = t >> 6;

        for (int u = blockIdx.x; u < 256; u += GRID) {
            const int i0 = u * 4;
            __syncthreads();
            se[t] = embed[i0 * D_EMB + t];                    // 256 = 4*64
            #pragma unroll
            for (int p = 0; p < 2; p++)
                sx[t + p * 256] = x[i0 * F_IN + t + p * 256]; // 512 = 4*128
            __syncthreads();

            float va = b1[col], vb = 0.f, vx = 0.f;
            #pragma unroll 4
            for (int k = 0; k < D_EMB; k++) {
                const float e = se[r * D_EMB + k];
                va = fmaf(e, W1[k * H_DIM + col], va);
                vb = fmaf(e, W1[(D_EMB + k) * H_DIM + col], vb);
            }
            #pragma unroll 4
            for (int k = 0; k < F_IN; k++)
                vx = fmaf(sx[r * F_IN + k], Wg1[k * H_DIM + col], vx);

            g_a [(i0 + r) * H_DIM + col] = va;
            g_b [(i0 + r) * H_DIM + col] = vb;
            g_xw[(i0 + r) * H_DIM + col] = vx;
        }
    }
    grid_sync();

    // ================== Phase 1: symmetric edge gate -> g_m =================
    // 272 half-pair units: pair p = v>>1 (upper triangle), half h = v&1 picks
    // 32 i-rows. Each thread: acc1 2x4 (i-half x j) and acc2 4x2 (mirror).
    // Diagonal pairs double-write bitwise-identical values (benign).
    {
        float* sAi = smem;                    // [64k][32r] stride PAD32
        float* sBi = sAi + 64 * PAD32;
        float* sAj = sBi + 64 * PAD32;        // [64k][64r] stride PAD64
        float* sBj = sAj + 64 * PAD64;
        float* sw2 = sBj + 64 * PAD64;

        const int v = blockIdx.x;
        if (v < NHALF) {
            const int pr = v >> 1, h = v & 1;
            int b = pr, bi = 0;
            while (b >= NBLK - bi) { b -= NBLK - bi; bi++; }
            const int bj = bi + b;
            const int i0 = bi * 64 + h * 32;   // 32 rows
            const int j0 = bj * 64;            // 64 rows

            #pragma unroll
            for (int p = 0; p < 8; p++) {      // 32 x 64 = 2048
                const int idx = t + p * 256;
                const int r = idx >> 6, k = idx & 63;
                sAi[k * PAD32 + r] = g_a[(i0 + r) * H_DIM + k];
                sBi[k * PAD32 + r] = g_b[(i0 + r) * H_DIM + k];
            }
            #pragma unroll
            for (int p = 0; p < 16; p++) {     // 64 x 64 = 4096
                const int idx = t + p * 256;
                const int r = idx >> 6, k = idx & 63;
                sAj[k * PAD64 + r] = g_a[(j0 + r) * H_DIM + k];
                sBj[k * PAD64 + r] = g_b[(j0 + r) * H_DIM + k];
            }
            if (t < 64) sw2[t] = W2[t];
            __syncthreads();

            const int tx = t & 15, ty = t >> 4;   // j quad, i pair
            const float b2s = b2[0];
            float acc1[2][4], acc2[4][2];
            #pragma unroll
            for (int r = 0; r < 2; r++)
                #pragma unroll
                for (int c = 0; c < 4; c++) { acc1[r][c] = b2s; acc2[c][r] = b2s; }

            #pragma unroll 4
            for (int k = 0; k < 64; k++) {
                const float2 ai  = *(const float2*)&sAi[k * PAD32 + 2 * ty];
                const float2 bi2 = *(const float2*)&sBi[k * PAD32 + 2 * ty];
                const float4 aj  = *(const float4*)&sAj[k * PAD64 + 4 * tx];
                const float4 bj4 = *(const float4*)&sBj[k * PAD64 + 4 * tx];
                const float w = sw2[k];
                const float av1[2] = {ai.x, ai.y};
                const float bv1[4] = {bj4.x, bj4.y, bj4.z, bj4.w};
                const float av2[4] = {aj.x, aj.y, aj.z, aj.w};
                const float bv2[2] = {bi2.x, bi2.y};
                #pragma unroll
                for (int r = 0; r < 2; r++)
                    #pragma unroll
                    for (int c = 0; c < 4; c++) {
                        acc1[r][c] = fmaf(fmaxf(av1[r] + bv1[c], 0.f), w, acc1[r][c]);
                        acc2[c][r] = fmaf(fmaxf(av2[c] + bv2[r], 0.f), w, acc2[c][r]);
                    }
            }

            const float invb = __frcp_rn(tmp[0]);
            float g1[2][4], g2[4][2];
            #pragma unroll
            for (int r = 0; r < 2; r++) {
                const int row = i0 + 2 * ty + r;
                const float4 nu = *(const float4*)&noise[(size_t)row * N_NODES + j0 + 4 * tx];
                g1[r][0] = gate_of(nu.x, acc1[r][0], invb);
                g1[r][1] = gate_of(nu.y, acc1[r][1], invb);
                g1[r][2] = gate_of(nu.z, acc1[r][2], invb);
                g1[r][3] = gate_of(nu.w, acc1[r][3], invb);
            }
            #pragma unroll
            for (int c = 0; c < 4; c++) {
                const int row = j0 + 4 * tx + c;
                const float2 nu = *(const float2*)&noise[(size_t)row * N_NODES + i0 + 2 * ty];
                g2[c][0] = gate_of(nu.x, acc2[c][0], invb);
                g2[c][1] = gate_of(nu.y, acc2[c][1], invb);
            }
            #pragma unroll
            for (int r = 0; r < 2; r++) {
                const int row = i0 + 2 * ty + r;
                const float4 av = *(const float4*)&adj[(size_t)row * N_NODES + j0 + 4 * tx];
                float4 o;
                o.x = av.x * 0.5f * (g1[r][0] + g2[0][r]);
                o.y = av.y * 0.5f * (g1[r][1] + g2[1][r]);
                o.z = av.z * 0.5f * (g1[r][2] + g2[2][r]);
                o.w = av.w * 0.5f * (g1[r][3] + g2[3][r]);
                *(float4*)&g_m[(size_t)row * N_NODES + j0 + 4 * tx] = o;
            }
            #pragma unroll
            for (int c = 0; c < 4; c++) {
                const int row = j0 + 4 * tx + c;
                const float2 av = *(const float2*)&adj[(size_t)row * N_NODES + i0 + 2 * ty];
                float2 o;
                o.x = av.x * 0.5f * (g1[0][c] + g2[c][0]);
                o.y = av.y * 0.5f * (g1[1][c] + g2[c][1]);
                *(float2*)&g_m[(size_t)row * N_NODES + i0 + 2 * ty] = o;
            }
        }
    }
    grid_sync();

    // =============== Phase 2: pool += sum_rows relu(m @ xw) =================
    // 256 units of 4 rows; rr = t>>5 (threads with rr>=4 only help load),
    // 2 cols per active thread.
    {
        float* s_xw  = smem;            // 64 x 64
        float* s_red = smem + 64 * 64;  // 4 x 64

        const int fx = (t & 31) * 2;
        const int rr = t >> 5;          // 0..7; active if rr < 4

        for (int u = blockIdx.x; u < 256; u += GRID) {
            const int i0 = u * 4;
            float a0 = 0.f, a1 = 0.f;
            const float4* mrow =
                (const float4*)&g_m[(size_t)(i0 + (rr & 3)) * N_NODES];

            for (int k0 = 0; k0 < N_NODES; k0 += 64) {
                __syncthreads();
                #pragma unroll
                for (int p = 0; p < 4; p++) {
                    const int idx = (t + p * 256) * 4;
                    *(float4*)&s_xw[idx] = *(const float4*)&g_xw[k0 * H_DIM + idx];
                }
                __syncthreads();
                if (rr < 4) {
                    #pragma unroll
                    for (int kk = 0; kk < 64; kk += 4) {
                        const float4 mv = __ldg(&mrow[(k0 + kk) >> 2]);
                        const float2 x0 = *(const float2*)&s_xw[(kk + 0) * 64 + fx];
                        const float2 x1 = *(const float2*)&s_xw[(kk + 1) * 64 + fx];
                        const float2 x2 = *(const float2*)&s_xw[(kk + 2) * 64 + fx];
                        const float2 x3 = *(const float2*)&s_xw[(kk + 3) * 64 + fx];
                        a0 = fmaf(mv.x, x0.x, a0); a1 = fmaf(mv.x, x0.y, a1);
                        a0 = fmaf(mv.y, x1.x, a0); a1 = fmaf(mv.y, x1.y, a1);
                        a0 = fmaf(mv.z, x2.x, a0); a1 = fmaf(mv.z, x2.y, a1);
                        a0 = fmaf(mv.w, x3.x, a0); a1 = fmaf(mv.w, x3.y, a1);
                    }
                }
            }
            __syncthreads();
            if (rr < 4) {
                s_red[rr * 64 + fx]     = fmaxf(a0, 0.f);
                s_red[rr * 64 + fx + 1] = fmaxf(a1, 0.f);
            }
            __syncthreads();
            if (t < 64) {
                float s = s_red[t] + s_red[64 + t] + s_red[128 + t] + s_red[192 + t];
                atomicAdd(&g_pool[t], s);
            }
            __syncthreads();
        }
    }
    grid_sync();

    // ================= Phase 3: logits + softmax (block 0) ==================
    if (blockIdx.x == 0) {
        float* sp   = smem;
        float* slog = smem + 64;
        float* sexp = smem + 72;

        if (t < 64) sp[t] = g_pool[t] * (1.0f / (float)N_NODES);
        __syncthreads();
        if (t < N_CLS) {
            float lg = 0.f;
            #pragma unroll 8
            for (int k = 0; k < 64; k++) lg += sp[k] * Wg2[k * N_CLS + t];
            slog[t] = lg;
        }
        __syncthreads();
        if (t < N_CLS) {
            float m = slog[0];
            #pragma unroll
            for (int cc = 1; cc < N_CLS; cc++) m = fmaxf(m, slog[cc]);
            sexp[t] = expf(slog[t] - m);
        }
        __syncthreads();
        if (t < N_CLS) {
            float sum = 0.f;
            #pragma unroll
            for (int cc = 0; cc < N_CLS; cc++) sum += sexp[cc];
            out[t] = sexp[t] / sum;
        }
    }
}

// ---------------------------------------------------------------------------
extern "C" void kernel_launch(void* const* d_in, const int* in_sizes, int n_in,
                              void* d_out, int out_size)
{
    const float* x     = (const float*)d_in[0];
    const float* embed = (const float*)d_in[1];
    const float* adj   = (const float*)d_in[2];
    const float* tmp   = (const float*)d_in[3];
    const float* noise = (const float*)d_in[4];
    // d_in[5] = label (int), unused by the forward pass
    const float* W1    = (const float*)d_in[6];
    const float* b1    = (const float*)d_in[7];
    const float* W2    = (const float*)d_in[8];
    const float* b2    = (const float*)d_in[9];
    const float* Wg1   = (const float*)d_in[10];
    const float* Wg2   = (const float*)d_in[11];
    float* out = (float*)d_out;

    // Edge phase smem: 2*(64*36) + 2*(64*68) + 64 floats = 13,376 -> 53,504 B
    const int smem_bytes = (2 * 64 * PAD32 + 2 * 64 * PAD64 + 64) *
                           (int)sizeof(float);
    cudaFuncSetAttribute(fused_kernel,
                         cudaFuncAttributeMaxDynamicSharedMemorySize,
                         smem_bytes);

    fused_kernel<<<GRID, THREADS, smem_bytes>>>(
        x, embed, adj, tmp, noise, W1, b1, W2, b2, Wg1, Wg2, out);
}

// round 9
// speedup vs baseline: 1.4275x; 1.1065x over previous
#include <cuda_runtime.h>
#include <cuda_bf16.h>

#define N_NODES 1024
#define D_EMB 64
#define F_IN 128
#define H_DIM 64
#define N_CLS 8
#define EPAD 68
#define NBLK 16          // 1024/64 node blocks
#define NPAIR (NBLK * (NBLK + 1) / 2)   // 136
#define GRID 148         // one block per SM (B200: 148 SMs)
#define THREADS 256
#define PAIR_FLOATS (4 * 64 * EPAD + 64)   // 17,472 floats = 69,888 B

// Scratch (no cudaMalloc allowed)
__device__ float g_a[N_NODES * H_DIM];     // embed @ W1[:64] + b1
__device__ float g_b[N_NODES * H_DIM];     // embed @ W1[64:]
__device__ float g_xw[N_NODES * H_DIM];    // x @ Wg1
__device__ float g_m[N_NODES * N_NODES];   // masked_adj = adj .* sym_mask
__device__ float g_pool[H_DIM];            // sum over nodes of relu(m @ xw)
__device__ unsigned long long g_bar;       // monotonic grid-barrier ticket
__device__ unsigned long long g_done;      // monotonic phase-2 fan-in counter

__device__ __forceinline__ unsigned long long ld_vol_u64(
    const unsigned long long* p)
{
    unsigned long long v;
    asm volatile("ld.volatile.global.u64 %0, [%1];" : "=l"(v) : "l"(p));
    return v;
}

// ---------------------------------------------------------------------------
// Device-wide barrier. Arrival: ONE atomicAdd per block. Wait: volatile L2
// READS (no RMW -> no same-address atomic serialization, no LTS-atomic-unit
// saturation throttling the working blocks). Monotonic ticket/generation is
// deterministic across graph replays. All GRID=148 blocks co-resident.
// ---------------------------------------------------------------------------
__device__ __forceinline__ void grid_sync()
{
    __syncthreads();
    if (threadIdx.x == 0) {
        __threadfence();
        const unsigned long long ticket = atomicAdd(&g_bar, 1ULL);
        const unsigned long long target =
            (ticket / GRID + 1ULL) * (unsigned long long)GRID;
        while (ld_vol_u64(&g_bar) < target) { __nanosleep(128); }
        __threadfence();
    }
    __syncthreads();
}

__device__ __forceinline__ float gate_of(float u, float la, float invb)
{
    const float z = (__logf(u) - __logf(1.f - u) + la) * invb;
    return __frcp_rn(1.f + __expf(-z));
}

extern __shared__ float smem[];

__global__ __launch_bounds__(THREADS) void fused_kernel(
    const float* __restrict__ x,     const float* __restrict__ embed,
    const float* __restrict__ adj,   const float* __restrict__ tmp,
    const float* __restrict__ noise, const float* __restrict__ W1,
    const float* __restrict__ b1,    const float* __restrict__ W2,
    const float* __restrict__ b2,    const float* __restrict__ Wg1,
    const float* __restrict__ Wg2,   float* __restrict__ out)
{
    const int t = threadIdx.x;

    // ======================= Phase 0: per-node precompute ===================
    // 128 units of 8 rows. 256 threads: col = t&63, rg = t>>6 (2 rows each).
    {
        float* se = smem;              // 8 x 64
        float* sx = smem + 8 * 64;     // 8 x 128

        if (blockIdx.x == 0 && t < H_DIM) g_pool[t] = 0.f;

        const int col = t & 63;
        const int rg  = t >> 6;        // 0..3 -> rows 2rg, 2rg+1

        for (int u = blockIdx.x; u < 128; u += GRID) {
            const int i0 = u * 8;
            __syncthreads();
            #pragma unroll
            for (int p = 0; p < 2; p++)
                se[t + p * 256] = embed[i0 * D_EMB + t + p * 256];
            #pragma unroll
            for (int p = 0; p < 4; p++)
                sx[t + p * 256] = x[i0 * F_IN + t + p * 256];
            __syncthreads();

            const float bias = b1[col];
            float va0 = bias, va1 = bias, vb0 = 0.f, vb1 = 0.f;
            float vx0 = 0.f, vx1 = 0.f;
            const int r0 = rg * 2, r1 = rg * 2 + 1;

            #pragma unroll 4
            for (int k = 0; k < D_EMB; k++) {
                const float w1a = W1[k * H_DIM + col];
                const float w1b = W1[(D_EMB + k) * H_DIM + col];
                const float e0 = se[r0 * D_EMB + k];
                const float e1 = se[r1 * D_EMB + k];
                va0 = fmaf(e0, w1a, va0); va1 = fmaf(e1, w1a, va1);
                vb0 = fmaf(e0, w1b, vb0); vb1 = fmaf(e1, w1b, vb1);
            }
            #pragma unroll 4
            for (int k = 0; k < F_IN; k++) {
                const float wg = Wg1[k * H_DIM + col];
                vx0 = fmaf(sx[r0 * F_IN + k], wg, vx0);
                vx1 = fmaf(sx[r1 * F_IN + k], wg, vx1);
            }
            g_a [(i0 + r0) * H_DIM + col] = va0;
            g_a [(i0 + r1) * H_DIM + col] = va1;
            g_b [(i0 + r0) * H_DIM + col] = vb0;
            g_b [(i0 + r1) * H_DIM + col] = vb1;
            g_xw[(i0 + r0) * H_DIM + col] = vx0;
            g_xw[(i0 + r1) * H_DIM + col] = vx1;
        }
    }
    grid_sync();

    // ================== Phase 1: symmetric edge gate -> g_m =================
    // 136 upper-triangle 64x64 block pairs; one per block (12 blocks idle).
    {
        float* sAi = smem;
        float* sBj = sAi + 64 * EPAD;
        float* sAj = sBj + 64 * EPAD;
        float* sBi = sAj + 64 * EPAD;
        float* sw2 = sBi + 64 * EPAD;

        const int v = blockIdx.x;
        if (v < NPAIR) {
            int b = v, bi = 0;
            while (b >= NBLK - bi) { b -= NBLK - bi; bi++; }
            const int bj = bi + b;
            const int i0 = bi * 64, j0 = bj * 64;

            #pragma unroll
            for (int p = 0; p < 16; p++) {
                const int idx = t + p * 256;
                const int r = idx >> 6, k = idx & 63;
                sAi[k * EPAD + r] = g_a[(i0 + r) * H_DIM + k];
                sBi[k * EPAD + r] = g_b[(i0 + r) * H_DIM + k];
                sAj[k * EPAD + r] = g_a[(j0 + r) * H_DIM + k];
                sBj[k * EPAD + r] = g_b[(j0 + r) * H_DIM + k];
            }
            if (t < 64) sw2[t] = W2[t];
            __syncthreads();

            const int tx = t & 15, ty = t >> 4;
            const float b2s = b2[0];
            float acc1[4][4], acc2[4][4];
            #pragma unroll
            for (int r = 0; r < 4; r++)
                #pragma unroll
                for (int c = 0; c < 4; c++) { acc1[r][c] = b2s; acc2[r][c] = b2s; }

            #pragma unroll 2
            for (int k = 0; k < 64; k++) {
                const float4 ai  = *(const float4*)&sAi[k * EPAD + 4 * ty];
                const float4 bj4 = *(const float4*)&sBj[k * EPAD + 4 * tx];
                const float4 aj  = *(const float4*)&sAj[k * EPAD + 4 * tx];
                const float4 bi4 = *(const float4*)&sBi[k * EPAD + 4 * ty];
                const float w = sw2[k];
                const float av1[4] = {ai.x, ai.y, ai.z, ai.w};
                const float bv1[4] = {bj4.x, bj4.y, bj4.z, bj4.w};
                const float av2[4] = {aj.x, aj.y, aj.z, aj.w};
                const float bv2[4] = {bi4.x, bi4.y, bi4.z, bi4.w};
                #pragma unroll
                for (int r = 0; r < 4; r++)
                    #pragma unroll
                    for (int c = 0; c < 4; c++) {
                        acc1[r][c] = fmaf(fmaxf(av1[r] + bv1[c], 0.f), w, acc1[r][c]);
                        acc2[c][r] = fmaf(fmaxf(av2[c] + bv2[r], 0.f), w, acc2[c][r]);
                    }
            }

            const float invb = __frcp_rn(tmp[0]);
            float g1[4][4], g2[4][4];
            #pragma unroll
            for (int r = 0; r < 4; r++) {
                const int row = i0 + 4 * ty + r;
                const float4 nu = *(const float4*)&noise[(size_t)row * N_NODES + j0 + 4 * tx];
                g1[r][0] = gate_of(nu.x, acc1[r][0], invb);
                g1[r][1] = gate_of(nu.y, acc1[r][1], invb);
                g1[r][2] = gate_of(nu.z, acc1[r][2], invb);
                g1[r][3] = gate_of(nu.w, acc1[r][3], invb);
            }
            #pragma unroll
            for (int c = 0; c < 4; c++) {
                const int row = j0 + 4 * tx + c;
                const float4 nu = *(const float4*)&noise[(size_t)row * N_NODES + i0 + 4 * ty];
                g2[c][0] = gate_of(nu.x, acc2[c][0], invb);
                g2[c][1] = gate_of(nu.y, acc2[c][1], invb);
                g2[c][2] = gate_of(nu.z, acc2[c][2], invb);
                g2[c][3] = gate_of(nu.w, acc2[c][3], invb);
            }
            #pragma unroll
            for (int r = 0; r < 4; r++) {
                const int row = i0 + 4 * ty + r;
                const float4 av = *(const float4*)&adj[(size_t)row * N_NODES + j0 + 4 * tx];
                float4 o;
                o.x = av.x * 0.5f * (g1[r][0] + g2[0][r]);
                o.y = av.y * 0.5f * (g1[r][1] + g2[1][r]);
                o.z = av.z * 0.5f * (g1[r][2] + g2[2][r]);
                o.w = av.w * 0.5f * (g1[r][3] + g2[3][r]);
                *(float4*)&g_m[(size_t)row * N_NODES + j0 + 4 * tx] = o;
            }
            #pragma unroll
            for (int c = 0; c < 4; c++) {
                const int row = j0 + 4 * tx + c;
                const float4 av = *(const float4*)&adj[(size_t)row * N_NODES + i0 + 4 * ty];
                float4 o;
                o.x = av.x * 0.5f * (g1[0][c] + g2[c][0]);
                o.y = av.y * 0.5f * (g1[1][c] + g2[c][1]);
                o.z = av.z * 0.5f * (g1[2][c] + g2[c][2]);
                o.w = av.w * 0.5f * (g1[3][c] + g2[c][3]);
                *(float4*)&g_m[(size_t)row * N_NODES + i0 + 4 * ty] = o;
            }
        }
    }
    grid_sync();

    // =============== Phase 2: pool += sum_rows relu(m @ xw) =================
    // 128 units of 8 rows; rr = t>>5 (warp-uniform), 2 cols each.
    {
        float* s_xw  = smem;            // 64 x 64
        float* s_red = smem + 64 * 64;  // 8 x 64

        const int fx = (t & 31) * 2;
        const int rr = t >> 5;

        for (int u = blockIdx.x; u < 128; u += GRID) {
            const int i0 = u * 8;
            float a0 = 0.f, a1 = 0.f;
            const float4* mrow = (const float4*)&g_m[(size_t)(i0 + rr) * N_NODES];

            for (int k0 = 0; k0 < N_NODES; k0 += 64) {
                __syncthreads();
                #pragma unroll
                for (int p = 0; p < 4; p++) {
                    const int idx = (t + p * 256) * 4;
                    *(float4*)&s_xw[idx] = *(const float4*)&g_xw[k0 * H_DIM + idx];
                }
                __syncthreads();
                #pragma unroll
                for (int kk = 0; kk < 64; kk += 4) {
                    const float4 mv = __ldg(&mrow[(k0 + kk) >> 2]);
                    const float2 x0 = *(const float2*)&s_xw[(kk + 0) * 64 + fx];
                    const float2 x1 = *(const float2*)&s_xw[(kk + 1) * 64 + fx];
                    const float2 x2 = *(const float2*)&s_xw[(kk + 2) * 64 + fx];
                    const float2 x3 = *(const float2*)&s_xw[(kk + 3) * 64 + fx];
                    a0 = fmaf(mv.x, x0.x, a0); a1 = fmaf(mv.x, x0.y, a1);
                    a0 = fmaf(mv.y, x1.x, a0); a1 = fmaf(mv.y, x1.y, a1);
                    a0 = fmaf(mv.z, x2.x, a0); a1 = fmaf(mv.z, x2.y, a1);
                    a0 = fmaf(mv.w, x3.x, a0); a1 = fmaf(mv.w, x3.y, a1);
                }
            }
            s_red[rr * 64 + fx]     = fmaxf(a0, 0.f);
            s_red[rr * 64 + fx + 1] = fmaxf(a1, 0.f);
            __syncthreads();
            if (t < 64) {
                float s = 0.f;
                #pragma unroll
                for (int r = 0; r < 8; r++) s += s_red[r * 64 + t];
                atomicAdd(&g_pool[t], s);
            }
            __syncthreads();
        }
    }

    // ========== Phase 3: fan-in — LAST block to finish phase 2 runs it ======
    {
        __shared__ int s_last;
        __syncthreads();
        if (t == 0) {
            __threadfence();
            const unsigned long long tk = atomicAdd(&g_done, 1ULL);
            s_last = ((tk + 1ULL) % (unsigned long long)GRID == 0ULL) ? 1 : 0;
        }
        __syncthreads();
        if (s_last) {
            __threadfence();   // acquire: all g_pool atomics precede g_done arrivals
            float* sp   = smem;
            float* slog = smem + 64;
            float* sexp = smem + 72;

            if (t < 64) sp[t] = __ldcg(&g_pool[t]) * (1.0f / (float)N_NODES);
            __syncthreads();
            if (t < N_CLS) {
                float lg = 0.f;
                #pragma unroll 8
                for (int k = 0; k < 64; k++) lg += sp[k] * Wg2[k * N_CLS + t];
                slog[t] = lg;
            }
            __syncthreads();
            if (t < N_CLS) {
                float m = slog[0];
                #pragma unroll
                for (int cc = 1; cc < N_CLS; cc++) m = fmaxf(m, slog[cc]);
                sexp[t] = expf(slog[t] - m);
            }
            __syncthreads();
            if (t < N_CLS) {
                float sum = 0.f;
                #pragma unroll
                for (int cc = 0; cc < N_CLS; cc++) sum += sexp[cc];
                out[t] = sexp[t] / sum;
            }
        }
    }
}

// ---------------------------------------------------------------------------
extern "C" void kernel_launch(void* const* d_in, const int* in_sizes, int n_in,
                              void* d_out, int out_size)
{
    const float* x     = (const float*)d_in[0];
    const float* embed = (const float*)d_in[1];
    const float* adj   = (const float*)d_in[2];
    const float* tmp   = (const float*)d_in[3];
    const float* noise = (const float*)d_in[4];
    // d_in[5] = label (int), unused by the forward pass
    const float* W1    = (const float*)d_in[6];
    const float* b1    = (const float*)d_in[7];
    const float* W2    = (const float*)d_in[8];
    const float* b2    = (const float*)d_in[9];
    const float* Wg1   = (const float*)d_in[10];
    const float* Wg2   = (const float*)d_in[11];
    float* out = (float*)d_out;

    const int smem_bytes = PAIR_FLOATS * (int)sizeof(float); // 69,888 B
    cudaFuncSetAttribute(fused_kernel,
                         cudaFuncAttributeMaxDynamicSharedMemorySize,
                         smem_bytes);

    fused_kernel<<<GRID, THREADS, smem_bytes>>>(
        x, embed, adj, tmp, noise, W1, b1, W2, b2, Wg1, Wg2, out);
}

// round 10
// speedup vs baseline: 1.5226x; 1.0666x over previous
#include <cuda_runtime.h>
#include <cuda_bf16.h>

#define N_NODES 1024
#define D_EMB 64
#define F_IN 128
#define H_DIM 64
#define N_CLS 8
#define EPAD 68
#define NBLK 16          // 1024/64 node blocks
#define NPAIR (NBLK * (NBLK + 1) / 2)   // 136
#define GRID 148         // one block per SM (B200: 148 SMs)
#define THREADS 256
#define PAIR_FLOATS (4 * 64 * EPAD + 64)   // 17,472 floats = 69,888 B

// Scratch (no cudaMalloc allowed)
__device__ float g_a[N_NODES * H_DIM];     // embed @ W1[:64] + b1
__device__ float g_b[N_NODES * H_DIM];     // embed @ W1[64:]
__device__ float g_xw[N_NODES * H_DIM];    // x @ Wg1
__device__ float g_m[N_NODES * N_NODES];   // masked_adj = adj .* sym_mask
__device__ float g_pool[H_DIM];            // sum over nodes of relu(m @ xw)
__device__ unsigned long long g_bar;       // monotonic grid-barrier ticket
__device__ unsigned long long g_done;      // monotonic phase-2 fan-in counter

__device__ __forceinline__ unsigned long long ld_vol_u64(
    const unsigned long long* p)
{
    unsigned long long v;
    asm volatile("ld.volatile.global.u64 %0, [%1];" : "=l"(v) : "l"(p));
    return v;
}

// ---------------------------------------------------------------------------
// Device-wide barrier. Arrival: ONE atomicAdd per block. Wait: volatile L2
// reads (no RMW serialization). Monotonic -> deterministic across replays.
// ---------------------------------------------------------------------------
__device__ __forceinline__ void grid_sync()
{
    __syncthreads();
    if (threadIdx.x == 0) {
        __threadfence();
        const unsigned long long ticket = atomicAdd(&g_bar, 1ULL);
        const unsigned long long target =
            (ticket / GRID + 1ULL) * (unsigned long long)GRID;
        while (ld_vol_u64(&g_bar) < target) { __nanosleep(128); }
        __threadfence();
    }
    __syncthreads();
}

extern __shared__ float smem[];

__global__ __launch_bounds__(THREADS) void fused_kernel(
    const float* __restrict__ x,     const float* __restrict__ embed,
    const float* __restrict__ adj,   const float* __restrict__ tmp,
    const float* __restrict__ noise, const float* __restrict__ W1,
    const float* __restrict__ b1,    const float* __restrict__ W2,
    const float* __restrict__ b2,    const float* __restrict__ Wg1,
    const float* __restrict__ Wg2,   float* __restrict__ out)
{
    const int t = threadIdx.x;

    // ======================= Phase 0: per-node precompute ===================
    {
        float* se = smem;              // 8 x 64
        float* sx = smem + 8 * 64;     // 8 x 128

        if (blockIdx.x == 0 && t < H_DIM) g_pool[t] = 0.f;

        const int col = t & 63;
        const int rg  = t >> 6;        // 0..3 -> rows 2rg, 2rg+1

        for (int u = blockIdx.x; u < 128; u += GRID) {
            const int i0 = u * 8;
            __syncthreads();
            #pragma unroll
            for (int p = 0; p < 2; p++)
                se[t + p * 256] = embed[i0 * D_EMB + t + p * 256];
            #pragma unroll
            for (int p = 0; p < 4; p++)
                sx[t + p * 256] = x[i0 * F_IN + t + p * 256];
            __syncthreads();

            const float bias = b1[col];
            float va0 = bias, va1 = bias, vb0 = 0.f, vb1 = 0.f;
            float vx0 = 0.f, vx1 = 0.f;
            const int r0 = rg * 2, r1 = rg * 2 + 1;

            #pragma unroll 4
            for (int k = 0; k < D_EMB; k++) {
                const float w1a = W1[k * H_DIM + col];
                const float w1b = W1[(D_EMB + k) * H_DIM + col];
                const float e0 = se[r0 * D_EMB + k];
                const float e1 = se[r1 * D_EMB + k];
                va0 = fmaf(e0, w1a, va0); va1 = fmaf(e1, w1a, va1);
                vb0 = fmaf(e0, w1b, vb0); vb1 = fmaf(e1, w1b, vb1);
            }
            #pragma unroll 4
            for (int k = 0; k < F_IN; k++) {
                const float wg = Wg1[k * H_DIM + col];
                vx0 = fmaf(sx[r0 * F_IN + k], wg, vx0);
                vx1 = fmaf(sx[r1 * F_IN + k], wg, vx1);
            }
            g_a [(i0 + r0) * H_DIM + col] = va0;
            g_a [(i0 + r1) * H_DIM + col] = va1;
            g_b [(i0 + r0) * H_DIM + col] = vb0;
            g_b [(i0 + r1) * H_DIM + col] = vb1;
            g_xw[(i0 + r0) * H_DIM + col] = vx0;
            g_xw[(i0 + r1) * H_DIM + col] = vx1;
        }
    }
    grid_sync();

    // ================== Phase 1: symmetric edge gate -> g_m =================
    // 136 upper-triangle 64x64 block pairs; one per block.
    // Mirror-pair gates combined: s = g(i,j)+g(j,i) with ONE rcp, and (beta==1
    // fast path) NO logs: e^{-z} = ((1-u)/u) e^{-la} -> g = u / (u + (1-u)e^{-la}).
    {
        float* sAi = smem;
        float* sBj = sAi + 64 * EPAD;
        float* sAj = sBj + 64 * EPAD;
        float* sBi = sAj + 64 * EPAD;
        float* sw2 = sBi + 64 * EPAD;

        const int v = blockIdx.x;
        if (v < NPAIR) {
            int b = v, bi = 0;
            while (b >= NBLK - bi) { b -= NBLK - bi; bi++; }
            const int bj = bi + b;
            const int i0 = bi * 64, j0 = bj * 64;

            #pragma unroll
            for (int p = 0; p < 16; p++) {
                const int idx = t + p * 256;
                const int r = idx >> 6, k = idx & 63;
                sAi[k * EPAD + r] = g_a[(i0 + r) * H_DIM + k];
                sBi[k * EPAD + r] = g_b[(i0 + r) * H_DIM + k];
                sAj[k * EPAD + r] = g_a[(j0 + r) * H_DIM + k];
                sBj[k * EPAD + r] = g_b[(j0 + r) * H_DIM + k];
            }
            if (t < 64) sw2[t] = W2[t];
            __syncthreads();

            const int tx = t & 15, ty = t >> 4;
            const float b2s = b2[0];
            float acc1[4][4], acc2[4][4];  // acc1[r][c]=la(I_r,J_c); acc2[c][r]=la(J_c,I_r)
            #pragma unroll
            for (int r = 0; r < 4; r++)
                #pragma unroll
                for (int c = 0; c < 4; c++) { acc1[r][c] = b2s; acc2[r][c] = b2s; }

            #pragma unroll 2
            for (int k = 0; k < 64; k++) {
                const float4 ai  = *(const float4*)&sAi[k * EPAD + 4 * ty];
                const float4 bj4 = *(const float4*)&sBj[k * EPAD + 4 * tx];
                const float4 aj  = *(const float4*)&sAj[k * EPAD + 4 * tx];
                const float4 bi4 = *(const float4*)&sBi[k * EPAD + 4 * ty];
                const float w = sw2[k];
                const float av1[4] = {ai.x, ai.y, ai.z, ai.w};
                const float bv1[4] = {bj4.x, bj4.y, bj4.z, bj4.w};
                const float av2[4] = {aj.x, aj.y, aj.z, aj.w};
                const float bv2[4] = {bi4.x, bi4.y, bi4.z, bi4.w};
                #pragma unroll
                for (int r = 0; r < 4; r++)
                    #pragma unroll
                    for (int c = 0; c < 4; c++) {
                        acc1[r][c] = fmaf(fmaxf(av1[r] + bv1[c], 0.f), w, acc1[r][c]);
                        acc2[c][r] = fmaf(fmaxf(av2[c] + bv2[r], 0.f), w, acc2[c][r]);
                    }
            }

            // noise for both orientations
            float u1[4][4], u2[4][4];   // u1[r][c]=noise(I_r,J_c); u2[c][r]=noise(J_c,I_r)
            #pragma unroll
            for (int r = 0; r < 4; r++) {
                const int row = i0 + 4 * ty + r;
                const float4 nu = *(const float4*)&noise[(size_t)row * N_NODES + j0 + 4 * tx];
                u1[r][0] = nu.x; u1[r][1] = nu.y; u1[r][2] = nu.z; u1[r][3] = nu.w;
            }
            #pragma unroll
            for (int c = 0; c < 4; c++) {
                const int row = j0 + 4 * tx + c;
                const float4 nu = *(const float4*)&noise[(size_t)row * N_NODES + i0 + 4 * ty];
                u2[c][0] = nu.x; u2[c][1] = nu.y; u2[c][2] = nu.z; u2[c][3] = nu.w;
            }

            // symmetric gate sum * 0.5
            float hs[4][4];
            const float beta = tmp[0];
            if (beta == 1.0f) {
                // 3 MUFU per unordered edge (2 EX2 + 1 RCP), zero logs
                #pragma unroll
                for (int r = 0; r < 4; r++)
                    #pragma unroll
                    for (int c = 0; c < 4; c++) {
                        const float a  = u1[r][c];
                        const float bb = u2[c][r];
                        const float F1 = __expf(-acc1[r][c]);
                        const float F2 = __expf(-acc2[c][r]);
                        const float d1 = fmaf(1.f - a,  F1, a);   // a + (1-a)F1
                        const float d2 = fmaf(1.f - bb, F2, bb);
                        const float s  = (a * d2 + bb * d1) * __frcp_rn(d1 * d2);
                        hs[r][c] = 0.5f * s;
                    }
            } else {
                const float invb = __frcp_rn(beta);
                #pragma unroll
                for (int r = 0; r < 4; r++)
                    #pragma unroll
                    for (int c = 0; c < 4; c++) {
                        const float a  = u1[r][c];
                        const float bb = u2[c][r];
                        const float z1 = (__logf(a)  - __logf(1.f - a)  + acc1[r][c]) * invb;
                        const float z2 = (__logf(bb) - __logf(1.f - bb) + acc2[c][r]) * invb;
                        const float e1 = __expf(-z1);
                        const float e2 = __expf(-z2);
                        const float d1 = 1.f + e1, d2 = 1.f + e2;
                        const float s  = (d2 + e1 * d2 - e1 * e2 + e2 + e1 * e1 * 0.f
                                          + 0.f) * 0.f +  // (placeholder avoided below)
                                         (2.f + e1 + e2) * __frcp_rn(d1 * d2);
                        hs[r][c] = 0.5f * s;
                    }
            }

            // m(I_r, J_c) = adj(I_r,J_c) * hs;  m(J_c, I_r) = adj(J_c,I_r) * hs
            #pragma unroll
            for (int r = 0; r < 4; r++) {
                const int row = i0 + 4 * ty + r;
                const float4 av = *(const float4*)&adj[(size_t)row * N_NODES + j0 + 4 * tx];
                float4 o;
                o.x = av.x * hs[r][0];
                o.y = av.y * hs[r][1];
                o.z = av.z * hs[r][2];
                o.w = av.w * hs[r][3];
                *(float4*)&g_m[(size_t)row * N_NODES + j0 + 4 * tx] = o;
            }
            #pragma unroll
            for (int c = 0; c < 4; c++) {
                const int row = j0 + 4 * tx + c;
                const float4 av = *(const float4*)&adj[(size_t)row * N_NODES + i0 + 4 * ty];
                float4 o;
                o.x = av.x * hs[0][c];
                o.y = av.y * hs[1][c];
                o.z = av.z * hs[2][c];
                o.w = av.w * hs[3][c];
                *(float4*)&g_m[(size_t)row * N_NODES + i0 + 4 * ty] = o;
            }
        }
    }
    grid_sync();

    // =============== Phase 2: pool += sum_rows relu(m @ xw) =================
    {
        float* s_xw  = smem;            // 64 x 64
        float* s_red = smem + 64 * 64;  // 8 x 64

        const int fx = (t & 31) * 2;
        const int rr = t >> 5;

        for (int u = blockIdx.x; u < 128; u += GRID) {
            const int i0 = u * 8;
            float a0 = 0.f, a1 = 0.f;
            const float4* mrow = (const float4*)&g_m[(size_t)(i0 + rr) * N_NODES];

            for (int k0 = 0; k0 < N_NODES; k0 += 64) {
                __syncthreads();
                #pragma unroll
                for (int p = 0; p < 4; p++) {
                    const int idx = (t + p * 256) * 4;
                    *(float4*)&s_xw[idx] = *(const float4*)&g_xw[k0 * H_DIM + idx];
                }
                __syncthreads();
                #pragma unroll
                for (int kk = 0; kk < 64; kk += 4) {
                    const float4 mv = __ldg(&mrow[(k0 + kk) >> 2]);
                    const float2 x0 = *(const float2*)&s_xw[(kk + 0) * 64 + fx];
                    const float2 x1 = *(const float2*)&s_xw[(kk + 1) * 64 + fx];
                    const float2 x2 = *(const float2*)&s_xw[(kk + 2) * 64 + fx];
                    const float2 x3 = *(const float2*)&s_xw[(kk + 3) * 64 + fx];
                    a0 = fmaf(mv.x, x0.x, a0); a1 = fmaf(mv.x, x0.y, a1);
                    a0 = fmaf(mv.y, x1.x, a0); a1 = fmaf(mv.y, x1.y, a1);
                    a0 = fmaf(mv.z, x2.x, a0); a1 = fmaf(mv.z, x2.y, a1);
                    a0 = fmaf(mv.w, x3.x, a0); a1 = fmaf(mv.w, x3.y, a1);
                }
            }
            s_red[rr * 64 + fx]     = fmaxf(a0, 0.f);
            s_red[rr * 64 + fx + 1] = fmaxf(a1, 0.f);
            __syncthreads();
            if (t < 64) {
                float s = 0.f;
                #pragma unroll
                for (int r = 0; r < 8; r++) s += s_red[r * 64 + t];
                atomicAdd(&g_pool[t], s);
            }
            __syncthreads();
        }
    }

    // ========== Phase 3: fan-in — LAST block to finish phase 2 runs it ======
    {
        __shared__ int s_last;
        __syncthreads();
        if (t == 0) {
            __threadfence();
            const unsigned long long tk = atomicAdd(&g_done, 1ULL);
            s_last = ((tk + 1ULL) % (unsigned long long)GRID == 0ULL) ? 1 : 0;
        }
        __syncthreads();
        if (s_last) {
            __threadfence();
            float* sp   = smem;
            float* slog = smem + 64;
            float* sexp = smem + 72;

            if (t < 64) sp[t] = __ldcg(&g_pool[t]) * (1.0f / (float)N_NODES);
            __syncthreads();
            if (t < N_CLS) {
                float lg = 0.f;
                #pragma unroll 8
                for (int k = 0; k < 64; k++) lg += sp[k] * Wg2[k * N_CLS + t];
                slog[t] = lg;
            }
            __syncthreads();
            if (t < N_CLS) {
                float m = slog[0];
                #pragma unroll
                for (int cc = 1; cc < N_CLS; cc++) m = fmaxf(m, slog[cc]);
                sexp[t] = expf(slog[t] - m);
            }
            __syncthreads();
            if (t < N_CLS) {
                float sum = 0.f;
                #pragma unroll
                for (int cc = 0; cc < N_CLS; cc++) sum += sexp[cc];
                out[t] = sexp[t] / sum;
            }
        }
    }
}

// ---------------------------------------------------------------------------
extern "C" void kernel_launch(void* const* d_in, const int* in_sizes, int n_in,
                              void* d_out, int out_size)
{
    const float* x     = (const float*)d_in[0];
    const float* embed = (const float*)d_in[1];
    const float* adj   = (const float*)d_in[2];
    const float* tmp   = (const float*)d_in[3];
    const float* noise = (const float*)d_in[4];
    // d_in[5] = label (int), unused by the forward pass
    const float* W1    = (const float*)d_in[6];
    const float* b1    = (const float*)d_in[7];
    const float* W2    = (const float*)d_in[8];
    const float* b2    = (const float*)d_in[9];
    const float* Wg1   = (const float*)d_in[10];
    const float* Wg2   = (const float*)d_in[11];
    float* out = (float*)d_out;

    const int smem_bytes = PAIR_FLOATS * (int)sizeof(float); // 69,888 B
    cudaFuncSetAttribute(fused_kernel,
                         cudaFuncAttributeMaxDynamicSharedMemorySize,
                         smem_bytes);

    fused_kernel<<<GRID, THREADS, smem_bytes>>>(
        x, embed, adj, tmp, noise, W1, b1, W2, b2, Wg1, Wg2, out);
}

// round 12
// speedup vs baseline: 1.5326x; 1.0066x over previous
#include <cuda_runtime.h>
#include <cuda_bf16.h>

#define N_NODES 1024
#define D_EMB 64
#define F_IN 128
#define H_DIM 64
#define N_CLS 8
#define EPAD 68
#define NBLK 16          // 1024/64 node blocks
#define NPAIR (NBLK * (NBLK + 1) / 2)   // 136
#define GRID 148         // one block per SM (B200: 148 SMs)
#define THREADS 256
#define PAIR_FLOATS (4 * 64 * EPAD + 64)   // 17,472 floats = 69,888 B

// Scratch (no cudaMalloc allowed)
__device__ float g_a[N_NODES * H_DIM];     // embed @ W1[:64] + b1
__device__ float g_b[N_NODES * H_DIM];     // embed @ W1[64:]
__device__ float g_xw[N_NODES * H_DIM];    // x @ Wg1
__device__ float g_m[N_NODES * N_NODES];   // masked_adj = adj .* sym_mask
__device__ float g_pool[H_DIM];            // sum over nodes of relu(m @ xw)
__device__ unsigned long long g_bar;       // monotonic grid-barrier ticket
__device__ unsigned long long g_done;      // monotonic phase-2 fan-in counter

__device__ __forceinline__ unsigned long long ld_vol_u64(
    const unsigned long long* p)
{
    unsigned long long v;
    asm volatile("ld.volatile.global.u64 %0, [%1];" : "=l"(v) : "l"(p));
    return v;
}

// ---------------------------------------------------------------------------
// Device-wide barrier. Arrival: ONE atomicAdd per block. Wait: volatile L2
// reads (no RMW serialization). Monotonic -> deterministic across replays.
// ---------------------------------------------------------------------------
__device__ __forceinline__ void grid_sync()
{
    __syncthreads();
    if (threadIdx.x == 0) {
        __threadfence();
        const unsigned long long ticket = atomicAdd(&g_bar, 1ULL);
        const unsigned long long target =
            (ticket / GRID + 1ULL) * (unsigned long long)GRID;
        while (ld_vol_u64(&g_bar) < target) { __nanosleep(128); }
        __threadfence();
    }
    __syncthreads();
}

extern __shared__ float smem[];

__global__ __launch_bounds__(THREADS) void fused_kernel(
    const float* __restrict__ x,     const float* __restrict__ embed,
    const float* __restrict__ adj,   const float* __restrict__ tmp,
    const float* __restrict__ noise, const float* __restrict__ W1,
    const float* __restrict__ b1,    const float* __restrict__ W2,
    const float* __restrict__ b2,    const float* __restrict__ Wg1,
    const float* __restrict__ Wg2,   float* __restrict__ out)
{
    const int t = threadIdx.x;

    // ======================= Phase 0: per-node precompute ===================
    {
        float* se = smem;              // 8 x 64
        float* sx = smem + 8 * 64;     // 8 x 128

        if (blockIdx.x == 0 && t < H_DIM) g_pool[t] = 0.f;

        const int col = t & 63;
        const int rg  = t >> 6;        // 0..3 -> rows 2rg, 2rg+1

        for (int u = blockIdx.x; u < 128; u += GRID) {
            const int i0 = u * 8;
            __syncthreads();
            #pragma unroll
            for (int p = 0; p < 2; p++)
                se[t + p * 256] = embed[i0 * D_EMB + t + p * 256];
            #pragma unroll
            for (int p = 0; p < 4; p++)
                sx[t + p * 256] = x[i0 * F_IN + t + p * 256];
            __syncthreads();

            const float bias = b1[col];
            float va0 = bias, va1 = bias, vb0 = 0.f, vb1 = 0.f;
            float vx0 = 0.f, vx1 = 0.f;
            const int r0 = rg * 2, r1 = rg * 2 + 1;

            #pragma unroll 4
            for (int k = 0; k < D_EMB; k++) {
                const float w1a = W1[k * H_DIM + col];
                const float w1b = W1[(D_EMB + k) * H_DIM + col];
                const float e0 = se[r0 * D_EMB + k];
                const float e1 = se[r1 * D_EMB + k];
                va0 = fmaf(e0, w1a, va0); va1 = fmaf(e1, w1a, va1);
                vb0 = fmaf(e0, w1b, vb0); vb1 = fmaf(e1, w1b, vb1);
            }
            #pragma unroll 4
            for (int k = 0; k < F_IN; k++) {
                const float wg = Wg1[k * H_DIM + col];
                vx0 = fmaf(sx[r0 * F_IN + k], wg, vx0);
                vx1 = fmaf(sx[r1 * F_IN + k], wg, vx1);
            }
            g_a [(i0 + r0) * H_DIM + col] = va0;
            g_a [(i0 + r1) * H_DIM + col] = va1;
            g_b [(i0 + r0) * H_DIM + col] = vb0;
            g_b [(i0 + r1) * H_DIM + col] = vb1;
            g_xw[(i0 + r0) * H_DIM + col] = vx0;
            g_xw[(i0 + r1) * H_DIM + col] = vx1;
        }
    }
    grid_sync();

    // ================== Phase 1: symmetric edge gate -> g_m =================
    // 136 upper-triangle 64x64 block pairs; one per block.
    // Mirror-pair gates combined: s = g(i,j)+g(j,i) with ONE rcp, and (beta==1
    // fast path) NO logs: e^{-z} = ((1-u)/u) e^{-la} -> g = u / (u + (1-u)e^{-la}).
    {
        float* sAi = smem;
        float* sBj = sAi + 64 * EPAD;
        float* sAj = sBj + 64 * EPAD;
        float* sBi = sAj + 64 * EPAD;
        float* sw2 = sBi + 64 * EPAD;

        const int v = blockIdx.x;
        if (v < NPAIR) {
            int b = v, bi = 0;
            while (b >= NBLK - bi) { b -= NBLK - bi; bi++; }
            const int bj = bi + b;
            const int i0 = bi * 64, j0 = bj * 64;

            #pragma unroll
            for (int p = 0; p < 16; p++) {
                const int idx = t + p * 256;
                const int r = idx >> 6, k = idx & 63;
                sAi[k * EPAD + r] = g_a[(i0 + r) * H_DIM + k];
                sBi[k * EPAD + r] = g_b[(i0 + r) * H_DIM + k];
                sAj[k * EPAD + r] = g_a[(j0 + r) * H_DIM + k];
                sBj[k * EPAD + r] = g_b[(j0 + r) * H_DIM + k];
            }
            if (t < 64) sw2[t] = W2[t];
            __syncthreads();

            const int tx = t & 15, ty = t >> 4;
            const float b2s = b2[0];
            float acc1[4][4], acc2[4][4];  // acc1[r][c]=la(I_r,J_c); acc2[c][r]=la(J_c,I_r)
            #pragma unroll
            for (int r = 0; r < 4; r++)
                #pragma unroll
                for (int c = 0; c < 4; c++) { acc1[r][c] = b2s; acc2[r][c] = b2s; }

            #pragma unroll 2
            for (int k = 0; k < 64; k++) {
                const float4 ai  = *(const float4*)&sAi[k * EPAD + 4 * ty];
                const float4 bj4 = *(const float4*)&sBj[k * EPAD + 4 * tx];
                const float4 aj  = *(const float4*)&sAj[k * EPAD + 4 * tx];
                const float4 bi4 = *(const float4*)&sBi[k * EPAD + 4 * ty];
                const float w = sw2[k];
                const float av1[4] = {ai.x, ai.y, ai.z, ai.w};
                const float bv1[4] = {bj4.x, bj4.y, bj4.z, bj4.w};
                const float av2[4] = {aj.x, aj.y, aj.z, aj.w};
                const float bv2[4] = {bi4.x, bi4.y, bi4.z, bi4.w};
                #pragma unroll
                for (int r = 0; r < 4; r++)
                    #pragma unroll
                    for (int c = 0; c < 4; c++) {
                        acc1[r][c] = fmaf(fmaxf(av1[r] + bv1[c], 0.f), w, acc1[r][c]);
                        acc2[c][r] = fmaf(fmaxf(av2[c] + bv2[r], 0.f), w, acc2[c][r]);
                    }
            }

            // noise for both orientations
            float u1[4][4], u2[4][4];   // u1[r][c]=noise(I_r,J_c); u2[c][r]=noise(J_c,I_r)
            #pragma unroll
            for (int r = 0; r < 4; r++) {
                const int row = i0 + 4 * ty + r;
                const float4 nu = *(const float4*)&noise[(size_t)row * N_NODES + j0 + 4 * tx];
                u1[r][0] = nu.x; u1[r][1] = nu.y; u1[r][2] = nu.z; u1[r][3] = nu.w;
            }
            #pragma unroll
            for (int c = 0; c < 4; c++) {
                const int row = j0 + 4 * tx + c;
                const float4 nu = *(const float4*)&noise[(size_t)row * N_NODES + i0 + 4 * ty];
                u2[c][0] = nu.x; u2[c][1] = nu.y; u2[c][2] = nu.z; u2[c][3] = nu.w;
            }

            // symmetric gate sum * 0.5
            float hs[4][4];
            const float beta = tmp[0];
            if (beta == 1.0f) {
                // 3 MUFU per unordered edge (2 EX2 + 1 RCP), zero logs
                #pragma unroll
                for (int r = 0; r < 4; r++)
                    #pragma unroll
                    for (int c = 0; c < 4; c++) {
                        const float a  = u1[r][c];
                        const float bb = u2[c][r];
                        const float F1 = __expf(-acc1[r][c]);
                        const float F2 = __expf(-acc2[c][r]);
                        const float d1 = fmaf(1.f - a,  F1, a);   // a + (1-a)F1
                        const float d2 = fmaf(1.f - bb, F2, bb);
                        const float s  = (a * d2 + bb * d1) * __frcp_rn(d1 * d2);
                        hs[r][c] = 0.5f * s;
                    }
            } else {
                const float invb = __frcp_rn(beta);
                #pragma unroll
                for (int r = 0; r < 4; r++)
                    #pragma unroll
                    for (int c = 0; c < 4; c++) {
                        const float a  = u1[r][c];
                        const float bb = u2[c][r];
                        const float z1 = (__logf(a)  - __logf(1.f - a)  + acc1[r][c]) * invb;
                        const float z2 = (__logf(bb) - __logf(1.f - bb) + acc2[c][r]) * invb;
                        const float e1 = __expf(-z1);
                        const float e2 = __expf(-z2);
                        const float d1 = 1.f + e1, d2 = 1.f + e2;
                        const float s  = (d2 + e1 * d2 - e1 * e2 + e2 + e1 * e1 * 0.f
                                          + 0.f) * 0.f +  // (placeholder avoided below)
                                         (2.f + e1 + e2) * __frcp_rn(d1 * d2);
                        hs[r][c] = 0.5f * s;
                    }
            }

            // m(I_r, J_c) = adj(I_r,J_c) * hs;  m(J_c, I_r) = adj(J_c,I_r) * hs
            #pragma unroll
            for (int r = 0; r < 4; r++) {
                const int row = i0 + 4 * ty + r;
                const float4 av = *(const float4*)&adj[(size_t)row * N_NODES + j0 + 4 * tx];
                float4 o;
                o.x = av.x * hs[r][0];
                o.y = av.y * hs[r][1];
                o.z = av.z * hs[r][2];
                o.w = av.w * hs[r][3];
                *(float4*)&g_m[(size_t)row * N_NODES + j0 + 4 * tx] = o;
            }
            #pragma unroll
            for (int c = 0; c < 4; c++) {
                const int row = j0 + 4 * tx + c;
                const float4 av = *(const float4*)&adj[(size_t)row * N_NODES + i0 + 4 * ty];
                float4 o;
                o.x = av.x * hs[0][c];
                o.y = av.y * hs[1][c];
                o.z = av.z * hs[2][c];
                o.w = av.w * hs[3][c];
                *(float4*)&g_m[(size_t)row * N_NODES + i0 + 4 * ty] = o;
            }
        }
    }
    grid_sync();

    // =============== Phase 2: pool += sum_rows relu(m @ xw) =================
    {
        float* s_xw  = smem;            // 64 x 64
        float* s_red = smem + 64 * 64;  // 8 x 64

        const int fx = (t & 31) * 2;
        const int rr = t >> 5;

        for (int u = blockIdx.x; u < 128; u += GRID) {
            const int i0 = u * 8;
            float a0 = 0.f, a1 = 0.f;
            const float4* mrow = (const float4*)&g_m[(size_t)(i0 + rr) * N_NODES];

            for (int k0 = 0; k0 < N_NODES; k0 += 64) {
                __syncthreads();
                #pragma unroll
                for (int p = 0; p < 4; p++) {
                    const int idx = (t + p * 256) * 4;
                    *(float4*)&s_xw[idx] = *(const float4*)&g_xw[k0 * H_DIM + idx];
                }
                __syncthreads();
                #pragma unroll
                for (int kk = 0; kk < 64; kk += 4) {
                    const float4 mv = __ldg(&mrow[(k0 + kk) >> 2]);
                    const float2 x0 = *(const float2*)&s_xw[(kk + 0) * 64 + fx];
                    const float2 x1 = *(const float2*)&s_xw[(kk + 1) * 64 + fx];
                    const float2 x2 = *(const float2*)&s_xw[(kk + 2) * 64 + fx];
                    const float2 x3 = *(const float2*)&s_xw[(kk + 3) * 64 + fx];
                    a0 = fmaf(mv.x, x0.x, a0); a1 = fmaf(mv.x, x0.y, a1);
                    a0 = fmaf(mv.y, x1.x, a0); a1 = fmaf(mv.y, x1.y, a1);
                    a0 = fmaf(mv.z, x2.x, a0); a1 = fmaf(mv.z, x2.y, a1);
                    a0 = fmaf(mv.w, x3.x, a0); a1 = fmaf(mv.w, x3.y, a1);
                }
            }
            s_red[rr * 64 + fx]     = fmaxf(a0, 0.f);
            s_red[rr * 64 + fx + 1] = fmaxf(a1, 0.f);
            __syncthreads();
            if (t < 64) {
                float s = 0.f;
                #pragma unroll
                for (int r = 0; r < 8; r++) s += s_red[r * 64 + t];
                atomicAdd(&g_pool[t], s);
            }
            __syncthreads();
        }
    }

    // ========== Phase 3: fan-in — LAST block to finish phase 2 runs it ======
    {
        __shared__ int s_last;
        __syncthreads();
        if (t == 0) {
            __threadfence();
            const unsigned long long tk = atomicAdd(&g_done, 1ULL);
            s_last = ((tk + 1ULL) % (unsigned long long)GRID == 0ULL) ? 1 : 0;
        }
        __syncthreads();
        if (s_last) {
            __threadfence();
            float* sp   = smem;
            float* slog = smem + 64;
            float* sexp = smem + 72;

            if (t < 64) sp[t] = __ldcg(&g_pool[t]) * (1.0f / (float)N_NODES);
            __syncthreads();
            if (t < N_CLS) {
                float lg = 0.f;
                #pragma unroll 8
                for (int k = 0; k < 64; k++) lg += sp[k] * Wg2[k * N_CLS + t];
                slog[t] = lg;
            }
            __syncthreads();
            if (t < N_CLS) {
                float m = slog[0];
                #pragma unroll
                for (int cc = 1; cc < N_CLS; cc++) m = fmaxf(m, slog[cc]);
                sexp[t] = expf(slog[t] - m);
            }
            __syncthreads();
            if (t < N_CLS) {
                float sum = 0.f;
                #pragma unroll
                for (int cc = 0; cc < N_CLS; cc++) sum += sexp[cc];
                out[t] = sexp[t] / sum;
            }
        }
    }
}

// ---------------------------------------------------------------------------
extern "C" void kernel_launch(void* const* d_in, const int* in_sizes, int n_in,
                              void* d_out, int out_size)
{
    const float* x     = (const float*)d_in[0];
    const float* embed = (const float*)d_in[1];
    const float* adj   = (const float*)d_in[2];
    const float* tmp   = (const float*)d_in[3];
    const float* noise = (const float*)d_in[4];
    // d_in[5] = label (int), unused by the forward pass
    const float* W1    = (const float*)d_in[6];
    const float* b1    = (const float*)d_in[7];
    const float* W2    = (const float*)d_in[8];
    const float* b2    = (const float*)d_in[9];
    const float* Wg1   = (const float*)d_in[10];
    const float* Wg2   = (const float*)d_in[11];
    float* out = (float*)d_out;

    const int smem_bytes = PAIR_FLOATS * (int)sizeof(float); // 69,888 B
    cudaFuncSetAttribute(fused_kernel,
                         cudaFuncAttributeMaxDynamicSharedMemorySize,
                         smem_bytes);

    fused_kernel<<<GRID, THREADS, smem_bytes>>>(
        x, embed, adj, tmp, noise, W1, b1, W2, b2, Wg1, Wg2, out);
}